// round 1
// baseline (speedup 1.0000x reference)
#include <cuda_runtime.h>
#include <math.h>
#include <stdint.h>

#define BATCHN 2
#define SEQ    1024
#define DMODEL 1024
#define DINNER 2048
#define DSTATE 16
#define DCONV  4
#define DTRANK 64
#define MROWS  (BATCHN * SEQ)   // 2048

// ---------------- scratch (device globals; no allocation allowed) -----------
__device__ float g_xz [2][MROWS][2 * DINNER];   // in_proj output (x-part + z-part)
__device__ float g_xi [2][MROWS][DINNER];       // conv+silu output
__device__ float g_dbc[2][MROWS][96];           // x_proj output (dt_raw | B | C)
__device__ float g_dt [2][MROWS][DINNER];       // softplus(dt)
__device__ float g_y  [2][MROWS][DINNER];       // scan output * silu(z)
__device__ float g_o  [2][MROWS][DMODEL];       // sigmoid(out_proj)

// ---------------- generic tiled GEMM:  C[M,N] = A[M,K] * W[N,K]^T -----------
// EPI: 0 = none, 1 = sigmoid, 2 = softplus(v + bias[n])
// reverse: row m of A maps to physical row (b*SEQ + (SEQ-1-l))  (time flip)
template<int EPI>
__global__ void gemm_tn(const float* __restrict__ A, const float* __restrict__ W,
                        float* __restrict__ C, int M, int N, int K,
                        int lda, int ldc, int reverse, const float* __restrict__ bias)
{
    __shared__ float As[16][64];
    __shared__ float Bs[16][64];
    const int m0 = blockIdx.y * 64;
    const int n0 = blockIdx.x * 64;
    const int tid = threadIdx.x;
    const int tx = tid & 15;        // 0..15  (n direction)
    const int ty = tid >> 4;        // 0..15  (m direction)

    float acc[4][4];
#pragma unroll
    for (int i = 0; i < 4; i++)
#pragma unroll
        for (int j = 0; j < 4; j++) acc[i][j] = 0.f;

    for (int k0 = 0; k0 < K; k0 += 16) {
#pragma unroll
        for (int i = 0; i < 4; i++) {
            int idx = tid + i * 256;
            int rl = idx >> 4;      // 0..63
            int kl = idx & 15;      // 0..15
            int m = m0 + rl;
            int mrow = m;
            if (reverse) mrow = (m & ~(SEQ - 1)) + (SEQ - 1 - (m & (SEQ - 1)));
            As[kl][rl] = A[(size_t)mrow * lda + k0 + kl];
            int n = n0 + rl;
            Bs[kl][rl] = (n < N) ? W[(size_t)n * K + k0 + kl] : 0.f;
        }
        __syncthreads();
#pragma unroll
        for (int k = 0; k < 16; k++) {
            float4 a4 = *reinterpret_cast<const float4*>(&As[k][ty * 4]);
            float4 b4 = *reinterpret_cast<const float4*>(&Bs[k][tx * 4]);
            float a[4] = {a4.x, a4.y, a4.z, a4.w};
            float b[4] = {b4.x, b4.y, b4.z, b4.w};
#pragma unroll
            for (int i = 0; i < 4; i++)
#pragma unroll
                for (int j = 0; j < 4; j++)
                    acc[i][j] = fmaf(a[i], b[j], acc[i][j]);
        }
        __syncthreads();
    }

#pragma unroll
    for (int i = 0; i < 4; i++) {
        int m = m0 + ty * 4 + i;
#pragma unroll
        for (int j = 0; j < 4; j++) {
            int n = n0 + tx * 4 + j;
            if (n < N) {
                float v = acc[i][j];
                if (EPI == 1) {
                    v = 1.f / (1.f + __expf(-v));
                } else if (EPI == 2) {
                    v += bias[n];
                    // stable softplus: max(v,0) + log1p(exp(-|v|))
                    v = fmaxf(v, 0.f) + log1pf(__expf(-fabsf(v)));
                }
                C[(size_t)m * ldc + n] = v;
            }
        }
    }
}

// ---------------- depthwise causal conv (k=4) + silu ------------------------
__global__ void conv_silu_kernel(const float* __restrict__ cw,
                                 const float* __restrict__ cb, int dir)
{
    int idx = blockIdx.x * blockDim.x + threadIdx.x;   // over MROWS * DINNER
    if (idx >= MROWS * DINNER) return;
    int c = idx % DINNER;
    int m = idx / DINNER;
    int l = m & (SEQ - 1);
    int mb = m - l;                 // batch base row
    float acc = cb[c];
#pragma unroll
    for (int k = 0; k < DCONV; k++) {
        int ls = l - (DCONV - 1) + k;
        if (ls >= 0) acc = fmaf(g_xz[dir][mb + ls][c], cw[c * DCONV + k], acc);
    }
    g_xi[dir][m][c] = acc / (1.f + __expf(-acc));      // silu
}

// ---------------- selective scan: 16 lanes per channel (one state each) -----
__global__ void scan_kernel(const float* __restrict__ AlogF, const float* __restrict__ DF,
                            const float* __restrict__ AlogB, const float* __restrict__ DB)
{
    int gid = blockIdx.x * blockDim.x + threadIdx.x;   // total 2*BATCHN*DINNER*16
    int s   = gid & (DSTATE - 1);
    int ci  = gid >> 4;
    int d   = ci % DINNER;
    int b   = (ci / DINNER) % BATCHN;
    int dir = ci / (DINNER * BATCHN);

    const float* Alog = dir ? AlogB : AlogF;
    const float* Dp   = dir ? DB    : DF;
    float Aval = -__expf(Alog[d * DSTATE + s]);
    float Dd   = Dp[d];

    float h = 0.f;
    int mbase = b * SEQ;
    for (int l = 0; l < SEQ; l++) {
        int m = mbase + l;
        float dtv = g_dt[dir][m][d];
        float xiv = g_xi[dir][m][d];
        float Bv  = g_dbc[dir][m][DTRANK + s];
        float Cv  = g_dbc[dir][m][DTRANK + DSTATE + s];
        h = fmaf(__expf(dtv * Aval), h, (dtv * xiv) * Bv);
        float p = h * Cv;
        // reduce across the 16 state lanes
        p += __shfl_xor_sync(0xffffffffu, p, 1);
        p += __shfl_xor_sync(0xffffffffu, p, 2);
        p += __shfl_xor_sync(0xffffffffu, p, 4);
        p += __shfl_xor_sync(0xffffffffu, p, 8);
        if (s == 0) {
            float y = p + xiv * Dd;
            float zv = g_xz[dir][m][DINNER + d];
            y *= zv / (1.f + __expf(-zv));             // * silu(z)
            g_y[dir][m][d] = y;
        }
    }
}

// ---------------- combine + layernorm + residual ----------------------------
__global__ void combine_ln_kernel(const float* __restrict__ x,
                                  const float* __restrict__ lng,
                                  const float* __restrict__ lnb,
                                  float* __restrict__ out)
{
    int row = blockIdx.x;                // b*SEQ + l
    int b = row / SEQ, l = row % SEQ;
    int rrev = b * SEQ + (SEQ - 1 - l);
    int tid = threadIdx.x;               // 256 threads, 4 elems each

    float v[4];
    float sum = 0.f, sq = 0.f;
#pragma unroll
    for (int i = 0; i < 4; i++) {
        int dm = tid + i * 256;
        float dv = 0.5f * (g_o[0][row][dm] + g_o[1][rrev][dm]);
        v[i] = dv;
        sum += dv;
        sq  += dv * dv;
    }
#pragma unroll
    for (int o = 16; o; o >>= 1) {
        sum += __shfl_xor_sync(0xffffffffu, sum, o);
        sq  += __shfl_xor_sync(0xffffffffu, sq,  o);
    }
    __shared__ float ssum[8], ssq[8];
    if ((tid & 31) == 0) { ssum[tid >> 5] = sum; ssq[tid >> 5] = sq; }
    __syncthreads();
    float ts = 0.f, tq = 0.f;
#pragma unroll
    for (int i = 0; i < 8; i++) { ts += ssum[i]; tq += ssq[i]; }
    float mu  = ts * (1.f / DMODEL);
    float var = tq * (1.f / DMODEL) - mu * mu;
    float inv = rsqrtf(var + 1e-5f);
#pragma unroll
    for (int i = 0; i < 4; i++) {
        int dm = tid + i * 256;
        out[(size_t)row * DMODEL + dm] =
            fmaf((v[i] - mu) * inv, lng[dm], lnb[dm]) + x[(size_t)row * DMODEL + dm];
    }
}

// ---------------- launch ----------------------------------------------------
extern "C" void kernel_launch(void* const* d_in, const int* in_sizes, int n_in,
                              void* d_out, int out_size)
{
    const float* x = (const float*)d_in[0];
    // f_* : 1..9, b_* : 10..18, ln: 19,20
    const float* in_proj[2] = {(const float*)d_in[1],  (const float*)d_in[10]};
    const float* conv_w [2] = {(const float*)d_in[2],  (const float*)d_in[11]};
    const float* conv_b [2] = {(const float*)d_in[3],  (const float*)d_in[12]};
    const float* x_proj [2] = {(const float*)d_in[4],  (const float*)d_in[13]};
    const float* dt_w   [2] = {(const float*)d_in[5],  (const float*)d_in[14]};
    const float* dt_b   [2] = {(const float*)d_in[6],  (const float*)d_in[15]};
    const float* A_log  [2] = {(const float*)d_in[7],  (const float*)d_in[16]};
    const float* Dp     [2] = {(const float*)d_in[8],  (const float*)d_in[17]};
    const float* out_pr [2] = {(const float*)d_in[9],  (const float*)d_in[18]};
    const float* ln_g = (const float*)d_in[19];
    const float* ln_b = (const float*)d_in[20];
    float* out = (float*)d_out;

    float *p_xz, *p_xi, *p_dbc, *p_dt, *p_y, *p_o;
    cudaGetSymbolAddress((void**)&p_xz,  g_xz);
    cudaGetSymbolAddress((void**)&p_xi,  g_xi);
    cudaGetSymbolAddress((void**)&p_dbc, g_dbc);
    cudaGetSymbolAddress((void**)&p_dt,  g_dt);
    cudaGetSymbolAddress((void**)&p_y,   g_y);
    cudaGetSymbolAddress((void**)&p_o,   g_o);

    const size_t szXZ  = (size_t)MROWS * 2 * DINNER;
    const size_t szXI  = (size_t)MROWS * DINNER;
    const size_t szDBC = (size_t)MROWS * 96;
    const size_t szO   = (size_t)MROWS * DMODEL;

    for (int dir = 0; dir < 2; dir++) {
        // 1) in_proj GEMM: [2048 x 4096] = x(reversed for dir1) @ in_proj^T
        gemm_tn<0><<<dim3(2 * DINNER / 64, MROWS / 64), 256>>>(
            x, in_proj[dir], p_xz + dir * szXZ,
            MROWS, 2 * DINNER, DMODEL, DMODEL, 2 * DINNER, dir, nullptr);

        // 2) depthwise conv + silu
        conv_silu_kernel<<<(MROWS * DINNER + 255) / 256, 256>>>(conv_w[dir], conv_b[dir], dir);

        // 3) x_proj GEMM: [2048 x 96]
        gemm_tn<0><<<dim3(2, MROWS / 64), 256>>>(
            p_xi + dir * szXI, x_proj[dir], p_dbc + dir * szDBC,
            MROWS, 96, DINNER, DINNER, 96, 0, nullptr);

        // 4) dt GEMM + softplus: [2048 x 2048], K=64 (A = dbc first 64 cols, lda=96)
        gemm_tn<2><<<dim3(DINNER / 64, MROWS / 64), 256>>>(
            p_dbc + dir * szDBC, dt_w[dir], p_dt + dir * szXI,
            MROWS, DINNER, DTRANK, 96, DINNER, 0, dt_b[dir]);
    }

    // 5) selective scan (both dirs in one launch)
    scan_kernel<<<(2 * BATCHN * DINNER * DSTATE) / 256, 256>>>(
        A_log[0], Dp[0], A_log[1], Dp[1]);

    for (int dir = 0; dir < 2; dir++) {
        // 6) out_proj GEMM + sigmoid: [2048 x 1024]
        gemm_tn<1><<<dim3(DMODEL / 64, MROWS / 64), 256>>>(
            p_y + dir * szXI, out_pr[dir], p_o + dir * szO,
            MROWS, DMODEL, DINNER, DINNER, DMODEL, 0, nullptr);
    }

    // 7) combine dirs + layernorm + residual
    combine_ln_kernel<<<MROWS, 256>>>(x, ln_g, ln_b, out);
}

// round 2
// speedup vs baseline: 2.1898x; 2.1898x over previous
#include <cuda_runtime.h>
#include <math.h>
#include <stdint.h>

#define BATCHN 2
#define SEQ    1024
#define DMODEL 1024
#define DINNER 2048
#define DSTATE 16
#define DCONV  4
#define DTRANK 64
#define MROWS  (BATCHN * SEQ)   // 2048

// ---------------- scratch (device globals; no allocation allowed) -----------
__device__ float g_xz [2][MROWS][2 * DINNER];   // in_proj output (x-part + z-part)
__device__ float g_xi [2][MROWS][DINNER];       // conv+silu output
__device__ float g_dbc[2][MROWS][96];           // x_proj output (dt_raw | B | C)
__device__ float g_dt [2][MROWS][DINNER];       // softplus(dt)
__device__ float g_y  [2][MROWS][DINNER];       // scan output * silu(z)
__device__ float g_o  [2][MROWS][DMODEL];       // sigmoid(out_proj)

__device__ __forceinline__ uint32_t f2tf32(float f) {
    uint32_t r;
    asm("cvt.rna.tf32.f32 %0, %1;" : "=r"(r) : "f"(f));
    return r;
}

// ---------------- tf32 tensor-core GEMM:  C[M,N] = A[M,K] * W[N,K]^T --------
// EPI: 0 = none, 1 = sigmoid, 2 = softplus(v + bias[n])
// reverse: row m of A maps to physical row (b*SEQ + (SEQ-1-l))  (time flip)
// Requires: M % 128 == 0, K % 32 == 0. N may be ragged (guarded).
template<int EPI>
__global__ __launch_bounds__(256, 2)
void gemm_mma(const float* __restrict__ A, const float* __restrict__ W,
              float* __restrict__ C, int M, int N, int K,
              int lda, int ldc, int reverse, const float* __restrict__ bias)
{
    constexpr int BM = 128, BN = 128, BK = 32;
    constexpr int LDS_S = 36;                    // padded stride (bank-conflict free)
    __shared__ uint32_t As[BM][LDS_S];           // [m][k]  tf32 bits
    __shared__ uint32_t Bs[BN][LDS_S];           // [n][k]  tf32 bits

    const int tid  = threadIdx.x;
    const int lane = tid & 31;
    const int wid  = tid >> 5;
    const int wm   = wid >> 1;                   // 0..3   warp row  (32 rows)
    const int wn   = wid & 1;                    // 0..1   warp col  (64 cols)
    const int m0   = blockIdx.y * BM;
    const int n0   = blockIdx.x * BN;

    const int lq = lane >> 2;                    // 0..7
    const int lr = lane & 3;                     // 0..3

    float acc[2][8][4];
#pragma unroll
    for (int i = 0; i < 2; i++)
#pragma unroll
        for (int j = 0; j < 8; j++)
#pragma unroll
            for (int c = 0; c < 4; c++) acc[i][j][c] = 0.f;

    for (int k0 = 0; k0 < K; k0 += BK) {
        // ---- fill smem: 1024 float4 per tile, 4 per thread ----
#pragma unroll
        for (int i = 0; i < 4; i++) {
            int f  = tid + i * 256;
            int r  = f >> 3;                     // 0..127
            int c4 = (f & 7) * 4;                // 0,4,...,28
            // A
            int m = m0 + r;
            int mrow = m;
            if (reverse) mrow = (m & ~(SEQ - 1)) + (SEQ - 1 - (m & (SEQ - 1)));
            float4 av = *reinterpret_cast<const float4*>(&A[(size_t)mrow * lda + k0 + c4]);
            uint4 at = make_uint4(f2tf32(av.x), f2tf32(av.y), f2tf32(av.z), f2tf32(av.w));
            *reinterpret_cast<uint4*>(&As[r][c4]) = at;
            // B
            int n = n0 + r;
            float4 bv = make_float4(0.f, 0.f, 0.f, 0.f);
            if (n < N) bv = *reinterpret_cast<const float4*>(&W[(size_t)n * K + k0 + c4]);
            uint4 bt = make_uint4(f2tf32(bv.x), f2tf32(bv.y), f2tf32(bv.z), f2tf32(bv.w));
            *reinterpret_cast<uint4*>(&Bs[r][c4]) = bt;
        }
        __syncthreads();

#pragma unroll
        for (int ks = 0; ks < 4; ks++) {
            const int k = ks * 8;
            // A fragments: 2 m-tiles
            uint32_t af[2][4];
#pragma unroll
            for (int i = 0; i < 2; i++) {
                int mr = wm * 32 + i * 16 + lq;
                af[i][0] = As[mr    ][k + lr    ];
                af[i][1] = As[mr + 8][k + lr    ];
                af[i][2] = As[mr    ][k + lr + 4];
                af[i][3] = As[mr + 8][k + lr + 4];
            }
            // B fragments: 8 n-tiles
            uint32_t bf[8][2];
#pragma unroll
            for (int j = 0; j < 8; j++) {
                int nr = wn * 64 + j * 8 + lq;
                bf[j][0] = Bs[nr][k + lr    ];
                bf[j][1] = Bs[nr][k + lr + 4];
            }
#pragma unroll
            for (int i = 0; i < 2; i++)
#pragma unroll
                for (int j = 0; j < 8; j++) {
                    asm volatile(
                        "mma.sync.aligned.m16n8k8.row.col.f32.tf32.tf32.f32 "
                        "{%0,%1,%2,%3}, {%4,%5,%6,%7}, {%8,%9}, {%0,%1,%2,%3};"
                        : "+f"(acc[i][j][0]), "+f"(acc[i][j][1]),
                          "+f"(acc[i][j][2]), "+f"(acc[i][j][3])
                        : "r"(af[i][0]), "r"(af[i][1]), "r"(af[i][2]), "r"(af[i][3]),
                          "r"(bf[j][0]), "r"(bf[j][1]));
                }
        }
        __syncthreads();
    }

    // ---- epilogue ----
#pragma unroll
    for (int i = 0; i < 2; i++) {
        int mrow0 = m0 + wm * 32 + i * 16 + lq;
#pragma unroll
        for (int j = 0; j < 8; j++) {
            int n = n0 + wn * 64 + j * 8 + lr * 2;
            if (n >= N) continue;
#pragma unroll
            for (int half = 0; half < 2; half++) {     // rows lq and lq+8
                int m = mrow0 + half * 8;
                float v0 = acc[i][j][half * 2 + 0];
                float v1 = acc[i][j][half * 2 + 1];
                if (EPI == 1) {
                    v0 = 1.f / (1.f + __expf(-v0));
                    v1 = 1.f / (1.f + __expf(-v1));
                } else if (EPI == 2) {
                    v0 += bias[n];
                    v1 += bias[n + 1];
                    v0 = fmaxf(v0, 0.f) + log1pf(__expf(-fabsf(v0)));
                    v1 = fmaxf(v1, 0.f) + log1pf(__expf(-fabsf(v1)));
                }
                *reinterpret_cast<float2*>(&C[(size_t)m * ldc + n]) = make_float2(v0, v1);
            }
        }
    }
}

// ---------------- depthwise causal conv (k=4) + silu ------------------------
__global__ void conv_silu_kernel(const float* __restrict__ cw,
                                 const float* __restrict__ cb, int dir)
{
    int idx = blockIdx.x * blockDim.x + threadIdx.x;   // over MROWS * DINNER
    if (idx >= MROWS * DINNER) return;
    int c = idx % DINNER;
    int m = idx / DINNER;
    int l = m & (SEQ - 1);
    int mb = m - l;                 // batch base row
    float acc = cb[c];
#pragma unroll
    for (int k = 0; k < DCONV; k++) {
        int ls = l - (DCONV - 1) + k;
        if (ls >= 0) acc = fmaf(g_xz[dir][mb + ls][c], cw[c * DCONV + k], acc);
    }
    g_xi[dir][m][c] = acc / (1.f + __expf(-acc));      // silu
}

// ---------------- selective scan: 16 lanes per channel (one state each) -----
__global__ void scan_kernel(const float* __restrict__ AlogF, const float* __restrict__ DF,
                            const float* __restrict__ AlogB, const float* __restrict__ DB)
{
    int gid = blockIdx.x * blockDim.x + threadIdx.x;   // total 2*BATCHN*DINNER*16
    int s   = gid & (DSTATE - 1);
    int ci  = gid >> 4;
    int d   = ci % DINNER;
    int b   = (ci / DINNER) % BATCHN;
    int dir = ci / (DINNER * BATCHN);

    const float* Alog = dir ? AlogB : AlogF;
    const float* Dp   = dir ? DB    : DF;
    float Aval = -__expf(Alog[d * DSTATE + s]);
    float Dd   = Dp[d];

    float h = 0.f;
    int mbase = b * SEQ;
    for (int l = 0; l < SEQ; l++) {
        int m = mbase + l;
        float dtv = g_dt[dir][m][d];
        float xiv = g_xi[dir][m][d];
        float Bv  = g_dbc[dir][m][DTRANK + s];
        float Cv  = g_dbc[dir][m][DTRANK + DSTATE + s];
        h = fmaf(__expf(dtv * Aval), h, (dtv * xiv) * Bv);
        float p = h * Cv;
        // reduce across the 16 state lanes
        p += __shfl_xor_sync(0xffffffffu, p, 1);
        p += __shfl_xor_sync(0xffffffffu, p, 2);
        p += __shfl_xor_sync(0xffffffffu, p, 4);
        p += __shfl_xor_sync(0xffffffffu, p, 8);
        if (s == 0) {
            float y = p + xiv * Dd;
            float zv = g_xz[dir][m][DINNER + d];
            y *= zv / (1.f + __expf(-zv));             // * silu(z)
            g_y[dir][m][d] = y;
        }
    }
}

// ---------------- combine + layernorm + residual ----------------------------
__global__ void combine_ln_kernel(const float* __restrict__ x,
                                  const float* __restrict__ lng,
                                  const float* __restrict__ lnb,
                                  float* __restrict__ out)
{
    int row = blockIdx.x;                // b*SEQ + l
    int b = row / SEQ, l = row % SEQ;
    int rrev = b * SEQ + (SEQ - 1 - l);
    int tid = threadIdx.x;               // 256 threads, 4 elems each

    float v[4];
    float sum = 0.f, sq = 0.f;
#pragma unroll
    for (int i = 0; i < 4; i++) {
        int dm = tid + i * 256;
        float dv = 0.5f * (g_o[0][row][dm] + g_o[1][rrev][dm]);
        v[i] = dv;
        sum += dv;
        sq  += dv * dv;
    }
#pragma unroll
    for (int o = 16; o; o >>= 1) {
        sum += __shfl_xor_sync(0xffffffffu, sum, o);
        sq  += __shfl_xor_sync(0xffffffffu, sq,  o);
    }
    __shared__ float ssum[8], ssq[8];
    if ((tid & 31) == 0) { ssum[tid >> 5] = sum; ssq[tid >> 5] = sq; }
    __syncthreads();
    float ts = 0.f, tq = 0.f;
#pragma unroll
    for (int i = 0; i < 8; i++) { ts += ssum[i]; tq += ssq[i]; }
    float mu  = ts * (1.f / DMODEL);
    float var = tq * (1.f / DMODEL) - mu * mu;
    float inv = rsqrtf(var + 1e-5f);
#pragma unroll
    for (int i = 0; i < 4; i++) {
        int dm = tid + i * 256;
        out[(size_t)row * DMODEL + dm] =
            fmaf((v[i] - mu) * inv, lng[dm], lnb[dm]) + x[(size_t)row * DMODEL + dm];
    }
}

// ---------------- launch ----------------------------------------------------
extern "C" void kernel_launch(void* const* d_in, const int* in_sizes, int n_in,
                              void* d_out, int out_size)
{
    const float* x = (const float*)d_in[0];
    // f_* : 1..9, b_* : 10..18, ln: 19,20
    const float* in_proj[2] = {(const float*)d_in[1],  (const float*)d_in[10]};
    const float* conv_w [2] = {(const float*)d_in[2],  (const float*)d_in[11]};
    const float* conv_b [2] = {(const float*)d_in[3],  (const float*)d_in[12]};
    const float* x_proj [2] = {(const float*)d_in[4],  (const float*)d_in[13]};
    const float* dt_w   [2] = {(const float*)d_in[5],  (const float*)d_in[14]};
    const float* dt_b   [2] = {(const float*)d_in[6],  (const float*)d_in[15]};
    const float* A_log  [2] = {(const float*)d_in[7],  (const float*)d_in[16]};
    const float* Dp     [2] = {(const float*)d_in[8],  (const float*)d_in[17]};
    const float* out_pr [2] = {(const float*)d_in[9],  (const float*)d_in[18]};
    const float* ln_g = (const float*)d_in[19];
    const float* ln_b = (const float*)d_in[20];
    float* out = (float*)d_out;

    float *p_xz, *p_xi, *p_dbc, *p_dt, *p_y, *p_o;
    cudaGetSymbolAddress((void**)&p_xz,  g_xz);
    cudaGetSymbolAddress((void**)&p_xi,  g_xi);
    cudaGetSymbolAddress((void**)&p_dbc, g_dbc);
    cudaGetSymbolAddress((void**)&p_dt,  g_dt);
    cudaGetSymbolAddress((void**)&p_y,   g_y);
    cudaGetSymbolAddress((void**)&p_o,   g_o);

    const size_t szXZ  = (size_t)MROWS * 2 * DINNER;
    const size_t szXI  = (size_t)MROWS * DINNER;
    const size_t szDBC = (size_t)MROWS * 96;
    const size_t szO   = (size_t)MROWS * DMODEL;

    for (int dir = 0; dir < 2; dir++) {
        // 1) in_proj GEMM: [2048 x 4096] = x(reversed for dir1) @ in_proj^T
        gemm_mma<0><<<dim3(2 * DINNER / 128, MROWS / 128), 256>>>(
            x, in_proj[dir], p_xz + dir * szXZ,
            MROWS, 2 * DINNER, DMODEL, DMODEL, 2 * DINNER, dir, nullptr);

        // 2) depthwise conv + silu
        conv_silu_kernel<<<(MROWS * DINNER + 255) / 256, 256>>>(conv_w[dir], conv_b[dir], dir);

        // 3) x_proj GEMM: [2048 x 96]
        gemm_mma<0><<<dim3(1, MROWS / 128), 256>>>(
            p_xi + dir * szXI, x_proj[dir], p_dbc + dir * szDBC,
            MROWS, 96, DINNER, DINNER, 96, 0, nullptr);

        // 4) dt GEMM + softplus: [2048 x 2048], K=64 (A = dbc first 64 cols, lda=96)
        gemm_mma<2><<<dim3(DINNER / 128, MROWS / 128), 256>>>(
            p_dbc + dir * szDBC, dt_w[dir], p_dt + dir * szXI,
            MROWS, DINNER, DTRANK, 96, DINNER, 0, dt_b[dir]);
    }

    // 5) selective scan (both dirs in one launch)
    scan_kernel<<<(2 * BATCHN * DINNER * DSTATE) / 256, 256>>>(
        A_log[0], Dp[0], A_log[1], Dp[1]);

    for (int dir = 0; dir < 2; dir++) {
        // 6) out_proj GEMM + sigmoid: [2048 x 1024]
        gemm_mma<1><<<dim3(DMODEL / 128, MROWS / 128), 256>>>(
            p_y + dir * szXI, out_pr[dir], p_o + dir * szO,
            MROWS, DMODEL, DINNER, DINNER, DMODEL, 0, nullptr);
    }

    // 7) combine dirs + layernorm + residual
    combine_ln_kernel<<<MROWS, 256>>>(x, ln_g, ln_b, out);
}

// round 3
// speedup vs baseline: 2.2495x; 1.0273x over previous
#include <cuda_runtime.h>
#include <math.h>
#include <stdint.h>

#define BATCHN 2
#define SEQ    1024
#define DMODEL 1024
#define DINNER 2048
#define DSTATE 16
#define DCONV  4
#define DTRANK 64
#define MROWS  (BATCHN * SEQ)   // 2048

// ---------------- scratch (device globals; no allocation allowed) -----------
__device__ float g_xz [2][MROWS][2 * DINNER];   // in_proj output (x-part + z-part)
__device__ float g_xi [2][MROWS][DINNER];       // conv+silu output
__device__ float g_dbc[2][MROWS][96];           // x_proj output (dt_raw | B | C)
__device__ float g_dt [2][MROWS][DINNER];       // softplus(dt)
__device__ float g_y  [2][MROWS][DINNER];       // scan output * silu(z)
__device__ float g_o  [2][MROWS][DMODEL];       // sigmoid(out_proj)

__device__ __forceinline__ uint32_t f2tf32(float f) {
    uint32_t r;
    asm("cvt.rna.tf32.f32 %0, %1;" : "=r"(r) : "f"(f));
    return r;
}

__device__ __forceinline__ void cp16(float* dst, const float* src, int bytes) {
    uint32_t d = (uint32_t)__cvta_generic_to_shared(dst);
    asm volatile("cp.async.ca.shared.global [%0], [%1], 16, %2;"
                 :: "r"(d), "l"(src), "r"(bytes));
}

// ---------------- tf32 tensor-core GEMM (cp.async double-buffered) ----------
//  C[M,N] = A[M,K] * W[N,K]^T
// EPI: 0 = none, 1 = sigmoid, 2 = softplus(v + bias[n])
// reverse: row m of A maps to physical row (b*SEQ + (SEQ-1-l))  (time flip)
// Requires: M % 128 == 0, K % 32 == 0. N may be ragged (guarded).
#define GEMM_BM 128
#define GEMM_BN 128
#define GEMM_BK 32
#define GEMM_LDS 36
#define GEMM_SMEM_BYTES (4 * GEMM_BM * GEMM_LDS * 4)   // 2 bufs x (A,B) = 73728

template<int EPI>
__global__ __launch_bounds__(256, 2)
void gemm_mma(const float* __restrict__ A, const float* __restrict__ W,
              float* __restrict__ C, int M, int N, int K,
              int lda, int ldc, int reverse, const float* __restrict__ bias)
{
    constexpr int BM = GEMM_BM, BN = GEMM_BN, BK = GEMM_BK, LDS_S = GEMM_LDS;
    extern __shared__ float smem[];
    float* Asb[2] = { smem,                smem + BM * LDS_S };
    float* Bsb[2] = { smem + 2 * BM * LDS_S, smem + 2 * BM * LDS_S + BN * LDS_S };

    const int tid  = threadIdx.x;
    const int lane = tid & 31;
    const int wid  = tid >> 5;
    const int wm   = wid >> 1;                   // 0..3   warp row  (32 rows)
    const int wn   = wid & 1;                    // 0..1   warp col  (64 cols)
    const int m0   = blockIdx.y * BM;
    const int n0   = blockIdx.x * BN;
    const int lq = lane >> 2;                    // 0..7
    const int lr = lane & 3;                     // 0..3

    // per-thread fill coordinates (4 float4 each for A and B)
    const int fr  = tid >> 3;                    // 0..31 base row
    const int fc4 = (tid & 7) * 4;               // 0..28

    float acc[2][8][4];
#pragma unroll
    for (int i = 0; i < 2; i++)
#pragma unroll
        for (int j = 0; j < 8; j++)
#pragma unroll
            for (int c = 0; c < 4; c++) acc[i][j][c] = 0.f;

    const int KT = K / BK;

    // ---- fill: issue cp.async for tile kt into buffer buf ----
    auto fill = [&](int kt, int buf) {
        int k0 = kt * BK;
#pragma unroll
        for (int i = 0; i < 4; i++) {
            int r = fr + i * 32;
            int m = m0 + r;
            int mrow = m;
            if (reverse) mrow = (m & ~(SEQ - 1)) + (SEQ - 1 - (m & (SEQ - 1)));
            cp16(&Asb[buf][r * LDS_S + fc4], &A[(size_t)mrow * lda + k0 + fc4], 16);
            int n = n0 + r;
            const float* bs = &W[(size_t)(n < N ? n : 0) * K + k0 + fc4];
            cp16(&Bsb[buf][r * LDS_S + fc4], bs, (n < N) ? 16 : 0);
        }
    };

    fill(0, 0);
    asm volatile("cp.async.commit_group;");

    for (int kt = 0; kt < KT; kt++) {
        const int cur = kt & 1;
        if (kt + 1 < KT) {
            fill(kt + 1, cur ^ 1);
            asm volatile("cp.async.commit_group;");
            asm volatile("cp.async.wait_group 1;");
        } else {
            asm volatile("cp.async.wait_group 0;");
        }
        __syncthreads();

        const float* Ac = Asb[cur];
        const float* Bc = Bsb[cur];
#pragma unroll
        for (int ks = 0; ks < 4; ks++) {
            const int k = ks * 8;
            uint32_t af[2][4];
#pragma unroll
            for (int i = 0; i < 2; i++) {
                int mr = wm * 32 + i * 16 + lq;
                af[i][0] = f2tf32(Ac[ mr      * LDS_S + k + lr    ]);
                af[i][1] = f2tf32(Ac[(mr + 8) * LDS_S + k + lr    ]);
                af[i][2] = f2tf32(Ac[ mr      * LDS_S + k + lr + 4]);
                af[i][3] = f2tf32(Ac[(mr + 8) * LDS_S + k + lr + 4]);
            }
            uint32_t bf[8][2];
#pragma unroll
            for (int j = 0; j < 8; j++) {
                int nr = wn * 64 + j * 8 + lq;
                bf[j][0] = f2tf32(Bc[nr * LDS_S + k + lr    ]);
                bf[j][1] = f2tf32(Bc[nr * LDS_S + k + lr + 4]);
            }
#pragma unroll
            for (int i = 0; i < 2; i++)
#pragma unroll
                for (int j = 0; j < 8; j++) {
                    asm volatile(
                        "mma.sync.aligned.m16n8k8.row.col.f32.tf32.tf32.f32 "
                        "{%0,%1,%2,%3}, {%4,%5,%6,%7}, {%8,%9}, {%0,%1,%2,%3};"
                        : "+f"(acc[i][j][0]), "+f"(acc[i][j][1]),
                          "+f"(acc[i][j][2]), "+f"(acc[i][j][3])
                        : "r"(af[i][0]), "r"(af[i][1]), "r"(af[i][2]), "r"(af[i][3]),
                          "r"(bf[j][0]), "r"(bf[j][1]));
                }
        }
        __syncthreads();     // all warps done reading buffer before it is refilled
    }

    // ---- epilogue ----
#pragma unroll
    for (int i = 0; i < 2; i++) {
        int mrow0 = m0 + wm * 32 + i * 16 + lq;
#pragma unroll
        for (int j = 0; j < 8; j++) {
            int n = n0 + wn * 64 + j * 8 + lr * 2;
            if (n >= N) continue;
#pragma unroll
            for (int half = 0; half < 2; half++) {     // rows lq and lq+8
                int m = mrow0 + half * 8;
                float v0 = acc[i][j][half * 2 + 0];
                float v1 = acc[i][j][half * 2 + 1];
                if (EPI == 1) {
                    v0 = 1.f / (1.f + __expf(-v0));
                    v1 = 1.f / (1.f + __expf(-v1));
                } else if (EPI == 2) {
                    v0 += bias[n];
                    v1 += bias[n + 1];
                    v0 = fmaxf(v0, 0.f) + log1pf(__expf(-fabsf(v0)));
                    v1 = fmaxf(v1, 0.f) + log1pf(__expf(-fabsf(v1)));
                }
                *reinterpret_cast<float2*>(&C[(size_t)m * ldc + n]) = make_float2(v0, v1);
            }
        }
    }
}

// ---------------- depthwise causal conv (k=4) + silu ------------------------
__global__ void conv_silu_kernel(const float* __restrict__ cw,
                                 const float* __restrict__ cb, int dir)
{
    int idx = blockIdx.x * blockDim.x + threadIdx.x;   // over MROWS * DINNER
    if (idx >= MROWS * DINNER) return;
    int c = idx % DINNER;
    int m = idx / DINNER;
    int l = m & (SEQ - 1);
    int mb = m - l;                 // batch base row
    float acc = cb[c];
#pragma unroll
    for (int k = 0; k < DCONV; k++) {
        int ls = l - (DCONV - 1) + k;
        if (ls >= 0) acc = fmaf(g_xz[dir][mb + ls][c], cw[c * DCONV + k], acc);
    }
    g_xi[dir][m][c] = acc / (1.f + __expf(-acc));      // silu
}

// ---------------- selective scan: 16 lanes per channel (one state each) -----
__global__ void scan_kernel(const float* __restrict__ AlogF, const float* __restrict__ DF,
                            const float* __restrict__ AlogB, const float* __restrict__ DB)
{
    int gid = blockIdx.x * blockDim.x + threadIdx.x;   // total 2*BATCHN*DINNER*16
    int s   = gid & (DSTATE - 1);
    int ci  = gid >> 4;
    int d   = ci % DINNER;
    int b   = (ci / DINNER) % BATCHN;
    int dir = ci / (DINNER * BATCHN);

    const float* Alog = dir ? AlogB : AlogF;
    const float* Dp   = dir ? DB    : DF;
    float Aval = -__expf(Alog[d * DSTATE + s]);
    float Dd   = Dp[d];

    float h = 0.f;
    int mbase = b * SEQ;
    for (int l = 0; l < SEQ; l++) {
        int m = mbase + l;
        float dtv = g_dt[dir][m][d];
        float xiv = g_xi[dir][m][d];
        float Bv  = g_dbc[dir][m][DTRANK + s];
        float Cv  = g_dbc[dir][m][DTRANK + DSTATE + s];
        h = fmaf(__expf(dtv * Aval), h, (dtv * xiv) * Bv);
        float p = h * Cv;
        // reduce across the 16 state lanes
        p += __shfl_xor_sync(0xffffffffu, p, 1);
        p += __shfl_xor_sync(0xffffffffu, p, 2);
        p += __shfl_xor_sync(0xffffffffu, p, 4);
        p += __shfl_xor_sync(0xffffffffu, p, 8);
        if (s == 0) {
            float y = p + xiv * Dd;
            float zv = g_xz[dir][m][DINNER + d];
            y *= zv / (1.f + __expf(-zv));             // * silu(z)
            g_y[dir][m][d] = y;
        }
    }
}

// ---------------- combine + layernorm + residual ----------------------------
__global__ void combine_ln_kernel(const float* __restrict__ x,
                                  const float* __restrict__ lng,
                                  const float* __restrict__ lnb,
                                  float* __restrict__ out)
{
    int row = blockIdx.x;                // b*SEQ + l
    int b = row / SEQ, l = row % SEQ;
    int rrev = b * SEQ + (SEQ - 1 - l);
    int tid = threadIdx.x;               // 256 threads, 4 elems each

    float v[4];
    float sum = 0.f, sq = 0.f;
#pragma unroll
    for (int i = 0; i < 4; i++) {
        int dm = tid + i * 256;
        float dv = 0.5f * (g_o[0][row][dm] + g_o[1][rrev][dm]);
        v[i] = dv;
        sum += dv;
        sq  += dv * dv;
    }
#pragma unroll
    for (int o = 16; o; o >>= 1) {
        sum += __shfl_xor_sync(0xffffffffu, sum, o);
        sq  += __shfl_xor_sync(0xffffffffu, sq,  o);
    }
    __shared__ float ssum[8], ssq[8];
    if ((tid & 31) == 0) { ssum[tid >> 5] = sum; ssq[tid >> 5] = sq; }
    __syncthreads();
    float ts = 0.f, tq = 0.f;
#pragma unroll
    for (int i = 0; i < 8; i++) { ts += ssum[i]; tq += ssq[i]; }
    float mu  = ts * (1.f / DMODEL);
    float var = tq * (1.f / DMODEL) - mu * mu;
    float inv = rsqrtf(var + 1e-5f);
#pragma unroll
    for (int i = 0; i < 4; i++) {
        int dm = tid + i * 256;
        out[(size_t)row * DMODEL + dm] =
            fmaf((v[i] - mu) * inv, lng[dm], lnb[dm]) + x[(size_t)row * DMODEL + dm];
    }
}

// ---------------- launch ----------------------------------------------------
extern "C" void kernel_launch(void* const* d_in, const int* in_sizes, int n_in,
                              void* d_out, int out_size)
{
    const float* x = (const float*)d_in[0];
    // f_* : 1..9, b_* : 10..18, ln: 19,20
    const float* in_proj[2] = {(const float*)d_in[1],  (const float*)d_in[10]};
    const float* conv_w [2] = {(const float*)d_in[2],  (const float*)d_in[11]};
    const float* conv_b [2] = {(const float*)d_in[3],  (const float*)d_in[12]};
    const float* x_proj [2] = {(const float*)d_in[4],  (const float*)d_in[13]};
    const float* dt_w   [2] = {(const float*)d_in[5],  (const float*)d_in[14]};
    const float* dt_b   [2] = {(const float*)d_in[6],  (const float*)d_in[15]};
    const float* A_log  [2] = {(const float*)d_in[7],  (const float*)d_in[16]};
    const float* Dp     [2] = {(const float*)d_in[8],  (const float*)d_in[17]};
    const float* out_pr [2] = {(const float*)d_in[9],  (const float*)d_in[18]};
    const float* ln_g = (const float*)d_in[19];
    const float* ln_b = (const float*)d_in[20];
    float* out = (float*)d_out;

    float *p_xz, *p_xi, *p_dbc, *p_dt, *p_y, *p_o;
    cudaGetSymbolAddress((void**)&p_xz,  g_xz);
    cudaGetSymbolAddress((void**)&p_xi,  g_xi);
    cudaGetSymbolAddress((void**)&p_dbc, g_dbc);
    cudaGetSymbolAddress((void**)&p_dt,  g_dt);
    cudaGetSymbolAddress((void**)&p_y,   g_y);
    cudaGetSymbolAddress((void**)&p_o,   g_o);

    // opt-in to 72KB dynamic smem (host-side attribute set; pre-capture, free at replay)
    cudaFuncSetAttribute(gemm_mma<0>, cudaFuncAttributeMaxDynamicSharedMemorySize, GEMM_SMEM_BYTES);
    cudaFuncSetAttribute(gemm_mma<1>, cudaFuncAttributeMaxDynamicSharedMemorySize, GEMM_SMEM_BYTES);
    cudaFuncSetAttribute(gemm_mma<2>, cudaFuncAttributeMaxDynamicSharedMemorySize, GEMM_SMEM_BYTES);

    const size_t szXZ  = (size_t)MROWS * 2 * DINNER;
    const size_t szXI  = (size_t)MROWS * DINNER;
    const size_t szDBC = (size_t)MROWS * 96;
    const size_t szO   = (size_t)MROWS * DMODEL;

    for (int dir = 0; dir < 2; dir++) {
        // 1) in_proj GEMM: [2048 x 4096] = x(reversed for dir1) @ in_proj^T
        gemm_mma<0><<<dim3(2 * DINNER / 128, MROWS / 128), 256, GEMM_SMEM_BYTES>>>(
            x, in_proj[dir], p_xz + dir * szXZ,
            MROWS, 2 * DINNER, DMODEL, DMODEL, 2 * DINNER, dir, nullptr);

        // 2) depthwise conv + silu
        conv_silu_kernel<<<(MROWS * DINNER + 255) / 256, 256>>>(conv_w[dir], conv_b[dir], dir);

        // 3) x_proj GEMM: [2048 x 96]
        gemm_mma<0><<<dim3(1, MROWS / 128), 256, GEMM_SMEM_BYTES>>>(
            p_xi + dir * szXI, x_proj[dir], p_dbc + dir * szDBC,
            MROWS, 96, DINNER, DINNER, 96, 0, nullptr);

        // 4) dt GEMM + softplus: [2048 x 2048], K=64 (A = dbc first 64 cols, lda=96)
        gemm_mma<2><<<dim3(DINNER / 128, MROWS / 128), 256, GEMM_SMEM_BYTES>>>(
            p_dbc + dir * szDBC, dt_w[dir], p_dt + dir * szXI,
            MROWS, DINNER, DTRANK, 96, DINNER, 0, dt_b[dir]);
    }

    // 5) selective scan (both dirs in one launch)
    scan_kernel<<<(2 * BATCHN * DINNER * DSTATE) / 256, 256>>>(
        A_log[0], Dp[0], A_log[1], Dp[1]);

    for (int dir = 0; dir < 2; dir++) {
        // 6) out_proj GEMM + sigmoid: [2048 x 1024]
        gemm_mma<1><<<dim3(DMODEL / 128, MROWS / 128), 256, GEMM_SMEM_BYTES>>>(
            p_y + dir * szXI, out_pr[dir], p_o + dir * szO,
            MROWS, DMODEL, DINNER, DINNER, DMODEL, 0, nullptr);
    }

    // 7) combine dirs + layernorm + residual
    combine_ln_kernel<<<MROWS, 256>>>(x, ln_g, ln_b, out);
}